// round 1
// baseline (speedup 1.0000x reference)
#include <cuda_runtime.h>
#include <math.h>
#include <stdint.h>

// ---------------------------------------------------------------------------
// Problem constants
// ---------------------------------------------------------------------------
#define BQ      8
#define LQ      128
#define NIMG    1024          // BQ * LQ
#define DQ      256           // VID_FEAT + N_MFCC
#define EDQ     512           // 2*DQ
#define NSTQ    16
#define DTRQ    16
#define NLQ     4
#define VID_FEAT 196
#define N_MFCC   60

// ---------------------------------------------------------------------------
// Scratch (device globals; allocation-free per harness rules)
// ---------------------------------------------------------------------------
__device__ float g_pool1[(size_t)NIMG * 32 * 32 * 32];   // conv1+pool out
__device__ float g_feat [NIMG * 64];                     // conv2+pool+mean out
__device__ float g_xc   [NIMG * DQ];                     // concat features
__device__ float g_xf   [NIMG * DQ];                     // fwd mamba stream
__device__ float g_xn   [NIMG * DQ];                     // rmsnorm out
__device__ float g_xz   [NIMG * 2 * EDQ];                // in_proj out (x | z)
__device__ float g_xcs  [NIMG * EDQ];                    // conv+silu out
__device__ float g_dbc  [NIMG * 48];                     // x_proj out (dt|B|C)
__device__ float g_delta[NIMG * EDQ];
__device__ float g_ys   [NIMG * EDQ];                    // scan out, then gated y
__device__ float g_xb   [BQ * DQ];                       // bwd mamba stream (T=8)
__device__ float g_xlast[BQ * 2 * DQ];
__device__ float g_fc1  [BQ * DQ];

// ---------------------------------------------------------------------------
// conv1 (3->32, 3x3 SAME) + relu + maxpool2  : one block per image
// smem: image 12288 + w 864 + b 32 floats
// ---------------------------------------------------------------------------
__global__ void __launch_bounds__(256) k_conv1(const float* __restrict__ video,
                                               const float* __restrict__ w,
                                               const float* __restrict__ bias) {
    extern __shared__ float sm[];
    float* simg = sm;           // 12288
    float* sw   = sm + 12288;   // 864
    float* sb   = sw + 864;     // 32
    int n = blockIdx.x;
    const float* img = video + (size_t)n * 12288;
    for (int i = threadIdx.x; i < 12288; i += 256) simg[i] = img[i];
    for (int i = threadIdx.x; i < 864;   i += 256) sw[i] = w[i];
    if (threadIdx.x < 32) sb[threadIdx.x] = bias[threadIdx.x];
    __syncthreads();

    int lane = threadIdx.x & 31;
    int warp = threadIdx.x >> 5;     // 8 warps, 4 channels each
    int c0 = warp * 4;
    for (int pass = 0; pass < 32; ++pass) {
        int q = pass * 32 + lane;          // pooled pos 0..1023 (32x32)
        int py = q >> 5, px = q & 31;
        float patch[48];
#pragma unroll
        for (int ic = 0; ic < 3; ++ic)
#pragma unroll
            for (int dy = 0; dy < 4; ++dy) {
                int y = 2 * py - 1 + dy;
#pragma unroll
                for (int dx = 0; dx < 4; ++dx) {
                    int x = 2 * px - 1 + dx;
                    patch[ic * 16 + dy * 4 + dx] =
                        (y >= 0 && y < 64 && x >= 0 && x < 64)
                            ? simg[ic * 4096 + y * 64 + x] : 0.f;
                }
            }
#pragma unroll
        for (int cc = 0; cc < 4; ++cc) {
            int c = c0 + cc;
            float bb = sb[c];
            float a0 = bb, a1 = bb, a2 = bb, a3 = bb;
            const float* wc = sw + c * 27;
#pragma unroll
            for (int ic = 0; ic < 3; ++ic)
#pragma unroll
                for (int ky = 0; ky < 3; ++ky)
#pragma unroll
                    for (int kx = 0; kx < 3; ++kx) {
                        float wv = wc[ic * 9 + ky * 3 + kx];
                        a0 += patch[ic * 16 +  ky      * 4 + kx    ] * wv;
                        a1 += patch[ic * 16 +  ky      * 4 + kx + 1] * wv;
                        a2 += patch[ic * 16 + (ky + 1) * 4 + kx    ] * wv;
                        a3 += patch[ic * 16 + (ky + 1) * 4 + kx + 1] * wv;
                    }
            float mx = fmaxf(fmaxf(a0, a1), fmaxf(a2, a3));
            g_pool1[(((size_t)n * 32 + c) << 10) + q] = fmaxf(mx, 0.f);
        }
    }
}

// ---------------------------------------------------------------------------
// conv2 (32->64, 3x3 SAME) + relu + maxpool2 + spatial mean : block per image
// smem: input 32768 + w 18432 + b 64 floats  (205 KB dynamic)
// ---------------------------------------------------------------------------
__global__ void __launch_bounds__(512) k_conv2(const float* __restrict__ w,
                                               const float* __restrict__ bias) {
    extern __shared__ float sm[];
    float* sin_ = sm;            // 32768
    float* sw   = sm + 32768;    // 18432
    float* sb   = sw + 18432;    // 64
    int n = blockIdx.x;
    const float* src = g_pool1 + (size_t)n * 32768;
    for (int i = threadIdx.x; i < 32768; i += 512) sin_[i] = src[i];
    for (int i = threadIdx.x; i < 18432; i += 512) sw[i] = w[i];
    if (threadIdx.x < 64) sb[threadIdx.x] = bias[threadIdx.x];
    __syncthreads();

    int lane = threadIdx.x & 31;
    int warp = threadIdx.x >> 5;   // 16 warps, 4 channels each
    int c0 = warp * 4;
    float csum[4] = {0.f, 0.f, 0.f, 0.f};
    for (int pass = 0; pass < 8; ++pass) {
        int q = pass * 32 + lane;        // pooled pos 0..255 (16x16)
        int py = q >> 4, px = q & 15;
        float acc[4][4];
#pragma unroll
        for (int cc = 0; cc < 4; ++cc) {
            float bb = sb[c0 + cc];
            acc[cc][0] = bb; acc[cc][1] = bb; acc[cc][2] = bb; acc[cc][3] = bb;
        }
        for (int ic = 0; ic < 32; ++ic) {
            float patch[16];
#pragma unroll
            for (int dy = 0; dy < 4; ++dy) {
                int y = 2 * py - 1 + dy;
#pragma unroll
                for (int dx = 0; dx < 4; ++dx) {
                    int x = 2 * px - 1 + dx;
                    patch[dy * 4 + dx] = (y >= 0 && y < 32 && x >= 0 && x < 32)
                                             ? sin_[ic * 1024 + y * 32 + x] : 0.f;
                }
            }
#pragma unroll
            for (int cc = 0; cc < 4; ++cc) {
                const float* wc = sw + (c0 + cc) * 288 + ic * 9;
#pragma unroll
                for (int ky = 0; ky < 3; ++ky)
#pragma unroll
                    for (int kx = 0; kx < 3; ++kx) {
                        float wv = wc[ky * 3 + kx];
                        acc[cc][0] += patch[ ky      * 4 + kx    ] * wv;
                        acc[cc][1] += patch[ ky      * 4 + kx + 1] * wv;
                        acc[cc][2] += patch[(ky + 1) * 4 + kx    ] * wv;
                        acc[cc][3] += patch[(ky + 1) * 4 + kx + 1] * wv;
                    }
            }
        }
#pragma unroll
        for (int cc = 0; cc < 4; ++cc) {
            float mx = fmaxf(fmaxf(acc[cc][0], acc[cc][1]),
                             fmaxf(acc[cc][2], acc[cc][3]));
            csum[cc] += fmaxf(mx, 0.f);
        }
    }
#pragma unroll
    for (int cc = 0; cc < 4; ++cc)
#pragma unroll
        for (int off = 16; off > 0; off >>= 1)
            csum[cc] += __shfl_down_sync(0xffffffffu, csum[cc], off);
    if (lane == 0)
#pragma unroll
        for (int cc = 0; cc < 4; ++cc)
            g_feat[n * 64 + c0 + cc] = csum[cc] * (1.0f / 256.0f);
}

// ---------------------------------------------------------------------------
// CNN fc: feat (1024,64) @ fcw(196,64)^T + b -> g_xc[:, 0:196]
// ---------------------------------------------------------------------------
__global__ void __launch_bounds__(256) k_cnnfc(const float* __restrict__ fw,
                                               const float* __restrict__ fb) {
    __shared__ float sf[64];
    int n = blockIdx.x;
    if (threadIdx.x < 64) sf[threadIdx.x] = g_feat[n * 64 + threadIdx.x];
    __syncthreads();
    int j = threadIdx.x;
    if (j < VID_FEAT) {
        float acc = fb[j];
        const float* wr = fw + j * 64;
#pragma unroll
        for (int k = 0; k < 64; ++k) acc += sf[k] * wr[k];
        g_xc[(size_t)n * DQ + j] = acc;
    }
}

__global__ void k_audio(const float* __restrict__ a) {
    int i = blockIdx.x * 256 + threadIdx.x;
    if (i >= BQ * LQ * N_MFCC) return;
    int m = i % N_MFCC;
    int t = i / N_MFCC;
    g_xc[(size_t)t * DQ + VID_FEAT + m] = a[i];
}

__global__ void k_copy(const float* __restrict__ s, float* __restrict__ d, int n) {
    int i = blockIdx.x * 256 + threadIdx.x;
    if (i < n) d[i] = s[i];
}

__global__ void k_lastcol() {   // g_xb = g_xc[:, L-1, :]
    int i = blockIdx.x * 256 + threadIdx.x;
    if (i < BQ * DQ) {
        int b = i >> 8, d = i & 255;
        g_xb[i] = g_xc[(size_t)(b * LQ + LQ - 1) * DQ + d];
    }
}

__global__ void k_xlast() {     // concat(xf[:, -1], xb)
    int i = blockIdx.x * 256 + threadIdx.x;
    if (i < BQ * 2 * DQ) {
        int b = i >> 9, j = i & 511;
        g_xlast[i] = (j < DQ) ? g_xf[(size_t)(b * LQ + LQ - 1) * DQ + j]
                              : g_xb[b * DQ + j - DQ];
    }
}

// ---------------------------------------------------------------------------
// RMSNorm over D=256, one block per token
// ---------------------------------------------------------------------------
__global__ void __launch_bounds__(256) k_rms(const float* __restrict__ x,
                                             const float* __restrict__ w,
                                             float* __restrict__ out) {
    int t = blockIdx.x;
    float v = x[(size_t)t * DQ + threadIdx.x];
    float s = v * v;
#pragma unroll
    for (int off = 16; off > 0; off >>= 1) s += __shfl_xor_sync(~0u, s, off);
    __shared__ float red[8];
    if ((threadIdx.x & 31) == 0) red[threadIdx.x >> 5] = s;
    __syncthreads();
    float tot = red[0] + red[1] + red[2] + red[3] +
                red[4] + red[5] + red[6] + red[7];
    float inv = rsqrtf(tot * (1.0f / DQ) + 1e-5f);
    out[(size_t)t * DQ + threadIdx.x] = v * inv * w[threadIdx.x];
}

// ---------------------------------------------------------------------------
// Generic SGEMM: C[M,N] = A[M,K] @ B[N,K]^T (+bias) (+=C if accum)
// 64x64 tile, BK=16, 256 threads, 4x4 per thread
// ---------------------------------------------------------------------------
__global__ void __launch_bounds__(256) k_gemm(const float* __restrict__ A, int lda,
                                              const float* __restrict__ Bw, int ldb,
                                              float* __restrict__ C, int ldc,
                                              int M, int N, int K,
                                              const float* __restrict__ bias,
                                              int accum) {
    __shared__ float As[16][68];
    __shared__ float Bs[16][68];
    int m0 = blockIdx.y * 64, n0 = blockIdx.x * 64;
    int ty = threadIdx.x >> 4, tx = threadIdx.x & 15;
    float acc[4][4] = {};
    for (int k0 = 0; k0 < K; k0 += 16) {
        for (int i = threadIdx.x; i < 1024; i += 256) {
            int r = i >> 4, kk = i & 15;
            int gk = k0 + kk;
            As[kk][r] = (m0 + r < M && gk < K) ? A[(size_t)(m0 + r) * lda + gk] : 0.f;
            Bs[kk][r] = (n0 + r < N && gk < K) ? Bw[(size_t)(n0 + r) * ldb + gk] : 0.f;
        }
        __syncthreads();
#pragma unroll
        for (int kk = 0; kk < 16; ++kk) {
            float4 av = *reinterpret_cast<const float4*>(&As[kk][ty * 4]);
            float4 bv = *reinterpret_cast<const float4*>(&Bs[kk][tx * 4]);
            float a[4] = {av.x, av.y, av.z, av.w};
            float b[4] = {bv.x, bv.y, bv.z, bv.w};
#pragma unroll
            for (int i = 0; i < 4; ++i)
#pragma unroll
                for (int j = 0; j < 4; ++j) acc[i][j] += a[i] * b[j];
        }
        __syncthreads();
    }
#pragma unroll
    for (int i = 0; i < 4; ++i) {
        int r = m0 + ty * 4 + i;
        if (r >= M) continue;
#pragma unroll
        for (int j = 0; j < 4; ++j) {
            int c = n0 + tx * 4 + j;
            if (c >= N) continue;
            float v = acc[i][j];
            if (bias) v += bias[c];
            if (accum) v += C[(size_t)r * ldc + c];
            C[(size_t)r * ldc + c] = v;
        }
    }
}

// ---------------------------------------------------------------------------
// causal depthwise conv4 + silu   (reads g_xz x-half, writes g_xcs)
// ---------------------------------------------------------------------------
__global__ void k_convsilu(const float* __restrict__ cw,
                           const float* __restrict__ cb, int T, int Lc) {
    int i = blockIdx.x * 256 + threadIdx.x;
    if (i >= T * EDQ) return;
    int t = i >> 9, e = i & 511;
    int l = t % Lc;
    float acc = cb[e];
#pragma unroll
    for (int k = 0; k < 4; ++k) {
        int li = l + k - 3;
        if (li >= 0) acc += g_xz[(size_t)(t + k - 3) * 1024 + e] * cw[e * 4 + k];
    }
    acc = acc / (1.f + __expf(-acc));
    g_xcs[i] = acc;
}

__global__ void k_softplus(int n) {
    int i = blockIdx.x * 256 + threadIdx.x;
    if (i < n) {
        float x = g_delta[i];
        g_delta[i] = (x > 20.f) ? x : log1pf(__expf(x));
    }
}

// ---------------------------------------------------------------------------
// Selective scan: thread per (b, e) channel, 16 states in registers
// ---------------------------------------------------------------------------
__global__ void __launch_bounds__(128) k_scan(const float* __restrict__ A_log, int Lc) {
    int e = blockIdx.x * 128 + threadIdx.x;
    int b = blockIdx.y;
    float negA[NSTQ];
#pragma unroll
    for (int n = 0; n < NSTQ; ++n) negA[n] = -__expf(A_log[e * NSTQ + n]);
    float h[NSTQ];
#pragma unroll
    for (int n = 0; n < NSTQ; ++n) h[n] = 0.f;
    for (int t = 0; t < Lc; ++t) {
        size_t idx = (size_t)(b * Lc + t);
        float dlt = g_delta[idx * EDQ + e];
        float xv  = g_xcs[idx * EDQ + e];
        const float* bc = g_dbc + idx * 48;
        float dx = dlt * xv;
        float y = 0.f;
#pragma unroll
        for (int n = 0; n < NSTQ; ++n) {
            float hn = __expf(dlt * negA[n]) * h[n] + dx * __ldg(bc + 16 + n);
            h[n] = hn;
            y += hn * __ldg(bc + 32 + n);
        }
        g_ys[idx * EDQ + e] = y;
    }
}

__global__ void k_gate(const float* __restrict__ Dp, int T) {
    int i = blockIdx.x * 256 + threadIdx.x;
    if (i >= T * EDQ) return;
    int t = i >> 9, e = i & 511;
    float z = g_xz[(size_t)t * 1024 + EDQ + e];
    float sz = z / (1.f + __expf(-z));
    g_ys[i] = (g_ys[i] + Dp[e] * g_xcs[i]) * sz;
}

// ---------------------------------------------------------------------------
// Host-side driver
// ---------------------------------------------------------------------------
static float* symf(const void* s) {
    void* p = nullptr;
    cudaGetSymbolAddress(&p, s);
    return (float*)p;
}

static void mamba_layer(float* x, const float* const* p, int l, int Bsz, int Lc) {
    const float* norm_w = p[0] + (size_t)l * DQ;
    const float* in_w   = p[1] + (size_t)l * 2 * EDQ * DQ;
    const float* conv_w = p[2] + (size_t)l * EDQ * 4;
    const float* conv_b = p[3] + (size_t)l * EDQ;
    const float* xp_w   = p[4] + (size_t)l * (DTRQ + 2 * NSTQ) * EDQ;
    const float* dt_w   = p[5] + (size_t)l * EDQ * DTRQ;
    const float* dt_b   = p[6] + (size_t)l * EDQ;
    const float* A_log  = p[7] + (size_t)l * EDQ * NSTQ;
    const float* Dp     = p[8] + (size_t)l * EDQ;
    const float* out_w  = p[9] + (size_t)l * DQ * EDQ;

    int T = Bsz * Lc;
    float* xn    = symf(g_xn);
    float* xz    = symf(g_xz);
    float* xcs   = symf(g_xcs);
    float* dbc   = symf(g_dbc);
    float* delta = symf(g_delta);
    float* ys    = symf(g_ys);

    int mt = (T + 63) / 64;
    k_rms<<<T, 256>>>(x, norm_w, xn);
    k_gemm<<<dim3(16, mt), 256>>>(xn, DQ, in_w, DQ, xz, 1024, T, 1024, DQ, nullptr, 0);
    k_convsilu<<<(T * EDQ + 255) / 256, 256>>>(conv_w, conv_b, T, Lc);
    k_gemm<<<dim3(1, mt), 256>>>(xcs, EDQ, xp_w, EDQ, dbc, 48, T, 48, EDQ, nullptr, 0);
    k_gemm<<<dim3(8, mt), 256>>>(dbc, 48, dt_w, DTRQ, delta, EDQ, T, EDQ, DTRQ, dt_b, 0);
    k_softplus<<<(T * EDQ + 255) / 256, 256>>>(T * EDQ);
    k_scan<<<dim3(EDQ / 128, Bsz), 128>>>(A_log, Lc);
    k_gate<<<(T * EDQ + 255) / 256, 256>>>(Dp, T);
    k_gemm<<<dim3(4, mt), 256>>>(ys, EDQ, out_w, EDQ, x, DQ, T, DQ, EDQ, nullptr, 1);
}

extern "C" void kernel_launch(void* const* d_in, const int* in_sizes, int n_in,
                              void* d_out, int out_size) {
    const float* video = (const float*)d_in[0];
    const float* audio = (const float*)d_in[1];
    const float* c1w = (const float*)d_in[2];
    const float* c1b = (const float*)d_in[3];
    const float* c2w = (const float*)d_in[4];
    const float* c2b = (const float*)d_in[5];
    const float* fcw = (const float*)d_in[6];
    const float* fcb = (const float*)d_in[7];
    const float* fwdp[10];
    const float* bwdp[10];
    for (int i = 0; i < 10; ++i) fwdp[i] = (const float*)d_in[8 + i];
    for (int i = 0; i < 10; ++i) bwdp[i] = (const float*)d_in[18 + i];
    const float* fc_w  = (const float*)d_in[28];
    const float* fc_b  = (const float*)d_in[29];
    const float* fc2_w = (const float*)d_in[30];
    const float* fc2_b = (const float*)d_in[31];
    float* out = (float*)d_out;

    cudaFuncSetAttribute(k_conv1, cudaFuncAttributeMaxDynamicSharedMemorySize, 53248);
    cudaFuncSetAttribute(k_conv2, cudaFuncAttributeMaxDynamicSharedMemorySize, 205312);

    // ---- CNN ----
    k_conv1<<<NIMG, 256, 52736>>>(video, c1w, c1b);
    k_conv2<<<NIMG, 512, 205056>>>(c2w, c2b);
    k_cnnfc<<<NIMG, 256>>>(fcw, fcb);
    k_audio<<<(BQ * LQ * N_MFCC + 255) / 256, 256>>>(audio);

    float* xc    = symf(g_xc);
    float* xf    = symf(g_xf);
    float* xb    = symf(g_xb);
    float* xlast = symf(g_xlast);
    float* fc1   = symf(g_fc1);

    // ---- forward Mamba (full sequence) ----
    k_copy<<<(NIMG * DQ + 255) / 256, 256>>>(xc, xf, NIMG * DQ);
    for (int l = 0; l < NLQ; ++l) mamba_layer(xf, fwdp, l, BQ, LQ);

    // ---- backward Mamba: causal => only the last timestep matters ----
    k_lastcol<<<(BQ * DQ + 255) / 256, 256>>>();
    for (int l = 0; l < NLQ; ++l) mamba_layer(xb, bwdp, l, BQ, 1);

    // ---- head ----
    k_xlast<<<(BQ * 2 * DQ + 255) / 256, 256>>>();
    k_gemm<<<dim3(4, 1), 256>>>(xlast, 2 * DQ, fc_w, 2 * DQ, fc1, DQ,
                                BQ, DQ, 2 * DQ, fc_b, 0);
    k_gemm<<<dim3(1, 1), 256>>>(fc1, DQ, fc2_w, DQ, out, 2,
                                BQ, 2, DQ, fc2_b, 0);
}

// round 2
// speedup vs baseline: 1.2673x; 1.2673x over previous
#include <cuda_runtime.h>
#include <math.h>
#include <stdint.h>

// ---------------------------------------------------------------------------
// Problem constants
// ---------------------------------------------------------------------------
#define BQ      8
#define LQ      128
#define NIMG    1024          // BQ * LQ
#define DQ      256           // VID_FEAT + N_MFCC
#define EDQ     512           // 2*DQ
#define NSTQ    16
#define DTRQ    16
#define NLQ     4
#define VID_FEAT 196
#define N_MFCC   60

// ---------------------------------------------------------------------------
// Scratch (device globals; allocation-free per harness rules)
// ---------------------------------------------------------------------------
__device__ float g_pool1[(size_t)NIMG * 32 * 32 * 32];   // conv1+pool out
__device__ float g_feat [NIMG * 64];                     // conv2+pool+mean out
__device__ float g_xc   [NIMG * DQ];                     // concat feats / fwd stream
__device__ float g_xn   [NIMG * DQ];                     // rmsnorm out
__device__ float g_xz   [NIMG * 2 * EDQ];                // in_proj out (x | z)
__device__ float g_xcs  [NIMG * EDQ];                    // conv+silu out
__device__ float g_dbc  [NIMG * 48];                     // x_proj out (dt|B|C)
__device__ float g_delta[NIMG * EDQ];                    // dt_proj out (pre-softplus)
__device__ float g_ys   [NIMG * EDQ];                    // scan out (gated)
__device__ float g_xb   [BQ * DQ];                       // bwd mamba stream (T=8)
__device__ float g_xlast[BQ * 2 * DQ];
__device__ float g_fc1  [BQ * DQ];

// ---------------------------------------------------------------------------
// conv1 (3->32, 3x3 SAME) + relu + maxpool2  : one block per image
// ---------------------------------------------------------------------------
__global__ void __launch_bounds__(256) k_conv1(const float* __restrict__ video,
                                               const float* __restrict__ w,
                                               const float* __restrict__ bias) {
    extern __shared__ float sm[];
    float* simg = sm;           // 12288
    float* sw   = sm + 12288;   // 864
    float* sb   = sw + 864;     // 32
    int n = blockIdx.x;
    const float* img = video + (size_t)n * 12288;
    for (int i = threadIdx.x; i < 12288; i += 256) simg[i] = img[i];
    for (int i = threadIdx.x; i < 864;   i += 256) sw[i] = w[i];
    if (threadIdx.x < 32) sb[threadIdx.x] = bias[threadIdx.x];
    __syncthreads();

    int lane = threadIdx.x & 31;
    int warp = threadIdx.x >> 5;     // 8 warps, 4 channels each
    int c0 = warp * 4;
    for (int pass = 0; pass < 32; ++pass) {
        int q = pass * 32 + lane;          // pooled pos 0..1023 (32x32)
        int py = q >> 5, px = q & 31;
        float patch[48];
#pragma unroll
        for (int ic = 0; ic < 3; ++ic)
#pragma unroll
            for (int dy = 0; dy < 4; ++dy) {
                int y = 2 * py - 1 + dy;
#pragma unroll
                for (int dx = 0; dx < 4; ++dx) {
                    int x = 2 * px - 1 + dx;
                    patch[ic * 16 + dy * 4 + dx] =
                        (y >= 0 && y < 64 && x >= 0 && x < 64)
                            ? simg[ic * 4096 + y * 64 + x] : 0.f;
                }
            }
#pragma unroll
        for (int cc = 0; cc < 4; ++cc) {
            int c = c0 + cc;
            float bb = sb[c];
            float a0 = bb, a1 = bb, a2 = bb, a3 = bb;
            const float* wc = sw + c * 27;
#pragma unroll
            for (int ic = 0; ic < 3; ++ic)
#pragma unroll
                for (int ky = 0; ky < 3; ++ky)
#pragma unroll
                    for (int kx = 0; kx < 3; ++kx) {
                        float wv = wc[ic * 9 + ky * 3 + kx];
                        a0 += patch[ic * 16 +  ky      * 4 + kx    ] * wv;
                        a1 += patch[ic * 16 +  ky      * 4 + kx + 1] * wv;
                        a2 += patch[ic * 16 + (ky + 1) * 4 + kx    ] * wv;
                        a3 += patch[ic * 16 + (ky + 1) * 4 + kx + 1] * wv;
                    }
            float mx = fmaxf(fmaxf(a0, a1), fmaxf(a2, a3));
            g_pool1[(((size_t)n * 32 + c) << 10) + q] = fmaxf(mx, 0.f);
        }
    }
}

// ---------------------------------------------------------------------------
// conv2 via tf32 mma.sync implicit GEMM + relu + maxpool2 + mean
// per image: C[1024 pos, 64 oc] = im2col[1024, 288] @ W[288, 64]
// smem: Xs [32][1032] (pad 8 -> conflict-free A frags)
//       Ws [288][72]  (pad 8 -> conflict-free B frags)
// ---------------------------------------------------------------------------
#define XS_FLOATS (32 * 1032)     // 33024
#define WS_FLOATS (288 * 72)      // 20736
#define C2_SMEM_BYTES ((XS_FLOATS + WS_FLOATS + 64 + 512) * 4)  // 217,344

__device__ __forceinline__ void mma_tf32(float* c, float a0, float a1,
                                         float a2, float a3,
                                         float b0, float b1) {
    asm volatile(
        "mma.sync.aligned.m16n8k8.row.col.f32.tf32.tf32.f32 "
        "{%0,%1,%2,%3}, {%4,%5,%6,%7}, {%8,%9}, {%0,%1,%2,%3};"
        : "+f"(c[0]), "+f"(c[1]), "+f"(c[2]), "+f"(c[3])
        : "r"(__float_as_uint(a0)), "r"(__float_as_uint(a1)),
          "r"(__float_as_uint(a2)), "r"(__float_as_uint(a3)),
          "r"(__float_as_uint(b0)), "r"(__float_as_uint(b1)));
}

__device__ __forceinline__ float to_tf32(float v) {
    uint32_t u;
    asm("cvt.rna.tf32.f32 %0, %1;" : "=r"(u) : "f"(v));
    return __uint_as_float(u);
}

__global__ void __launch_bounds__(256) k_conv2_mma(const float* __restrict__ w,
                                                   const float* __restrict__ bias) {
    extern __shared__ float sm[];
    float* Xs  = sm;                       // [ic][1032]
    float* Ws  = Xs + XS_FLOATS;           // [k][72], k = (ky*3+kx)*32+ic
    float* sb  = Ws + WS_FLOATS;           // 64
    float* red = sb + 64;                  // 8*64
    int n = blockIdx.x;
    int tid = threadIdx.x;

    const float* src = g_pool1 + (size_t)n * 32768;
    for (int i = tid; i < 32768; i += 256) {
        int ic = i >> 10, s = i & 1023;
        Xs[ic * 1032 + s] = to_tf32(src[i]);
    }
    for (int i = tid; i < 18432; i += 256) {
        int oc = i / 288, r = i % 288;
        int ic = r / 9, kk = r % 9;
        Ws[(kk * 32 + ic) * 72 + oc] = to_tf32(w[i]);
    }
    if (tid < 64) sb[tid] = bias[tid];
    __syncthreads();

    int lane = tid & 31, wp = tid >> 5;
    int g = lane >> 2, l4 = lane & 3;
    int ypair = wp >> 1, xh = wp & 1;
    int x0 = xh * 16;

    float cs[8][2];
#pragma unroll
    for (int j = 0; j < 8; ++j) { cs[j][0] = 0.f; cs[j][1] = 0.f; }

    for (int c = 0; c < 4; ++c) {          // 4 chunks of 8 y-rows
        int y = c * 8 + ypair * 2;         // tile A at row y, tile B at y+1
        float acc[2][8][4];
#pragma unroll
        for (int t = 0; t < 2; ++t)
#pragma unroll
            for (int j = 0; j < 8; ++j)
#pragma unroll
                for (int i = 0; i < 4; ++i) acc[t][j][i] = 0.f;

#pragma unroll
        for (int ky = 0; ky < 3; ++ky) {
            int yA = y + ky - 1;
            int yB = yA + 1;
            bool yokA = (unsigned)yA < 32u;
            bool yokB = (unsigned)yB < 32u;
#pragma unroll
            for (int kx = 0; kx < 3; ++kx) {
                int xg = x0 + g + kx - 1;
                bool p0 = (unsigned)xg < 32u;
                bool p1 = (unsigned)(xg + 8) < 32u;
                int sA = yA * 32 + xg;
                int sB = sA + 32;
                const float* xb = Xs + l4 * 1032;
                const float* wb = Ws + ((ky * 3 + kx) * 32 + l4) * 72 + g;
#pragma unroll
                for (int icq = 0; icq < 4; ++icq) {
                    const float* xp = xb + (icq * 8) * 1032;
                    float a0 = (yokA && p0) ? xp[sA]            : 0.f;
                    float a1 = (yokA && p1) ? xp[sA + 8]        : 0.f;
                    float a2 = (yokA && p0) ? xp[4 * 1032 + sA] : 0.f;
                    float a3 = (yokA && p1) ? xp[4 * 1032 + sA + 8] : 0.f;
                    float e0 = (yokB && p0) ? xp[sB]            : 0.f;
                    float e1 = (yokB && p1) ? xp[sB + 8]        : 0.f;
                    float e2 = (yokB && p0) ? xp[4 * 1032 + sB] : 0.f;
                    float e3 = (yokB && p1) ? xp[4 * 1032 + sB + 8] : 0.f;
                    const float* wq = wb + (icq * 8) * 72;
#pragma unroll
                    for (int j = 0; j < 8; ++j) {
                        float b0 = wq[8 * j];
                        float b1 = wq[4 * 72 + 8 * j];
                        mma_tf32(acc[0][j], a0, a1, a2, a3, b0, b1);
                        mma_tf32(acc[1][j], e0, e1, e2, e3, b0, b1);
                    }
                }
            }
        }

        // epilogue: y-max (in thread), x-max (shfl_xor 4), +bias, relu, accum
#pragma unroll
        for (int j = 0; j < 8; ++j)
#pragma unroll
            for (int i = 0; i < 4; ++i) {
                float m = fmaxf(acc[0][j][i], acc[1][j][i]);
                m = fmaxf(m, __shfl_xor_sync(0xffffffffu, m, 4));
                m = fmaxf(m + sb[8 * j + 2 * l4 + (i & 1)], 0.f);
                cs[j][i & 1] += m;   // every pooled value counted on 2 lanes
            }
    }

    // reduce over g (lanes stride 4)
#pragma unroll
    for (int j = 0; j < 8; ++j)
#pragma unroll
        for (int i = 0; i < 2; ++i) {
            float v = cs[j][i];
            v += __shfl_xor_sync(0xffffffffu, v, 16);
            v += __shfl_xor_sync(0xffffffffu, v, 8);
            v += __shfl_xor_sync(0xffffffffu, v, 4);
            cs[j][i] = v;
        }
    if (g == 0) {
#pragma unroll
        for (int j = 0; j < 8; ++j) {
            red[wp * 64 + 8 * j + 2 * l4]     = cs[j][0];
            red[wp * 64 + 8 * j + 2 * l4 + 1] = cs[j][1];
        }
    }
    __syncthreads();
    if (tid < 64) {
        float s = 0.f;
#pragma unroll
        for (int ww = 0; ww < 8; ++ww) s += red[ww * 64 + tid];
        g_feat[n * 64 + tid] = s * (1.0f / 512.0f);  // /256 mean, /2 dup-count
    }
}

// ---------------------------------------------------------------------------
// CNN fc: feat (1024,64) @ fcw(196,64)^T + b -> g_xc[:, 0:196]
// ---------------------------------------------------------------------------
__global__ void __launch_bounds__(256) k_cnnfc(const float* __restrict__ fw,
                                               const float* __restrict__ fb) {
    __shared__ float sf[64];
    int n = blockIdx.x;
    if (threadIdx.x < 64) sf[threadIdx.x] = g_feat[n * 64 + threadIdx.x];
    __syncthreads();
    int j = threadIdx.x;
    if (j < VID_FEAT) {
        float acc = fb[j];
        const float* wr = fw + j * 64;
#pragma unroll
        for (int k = 0; k < 64; ++k) acc += sf[k] * wr[k];
        g_xc[(size_t)n * DQ + j] = acc;
    }
}

__global__ void k_audio(const float* __restrict__ a) {
    int i = blockIdx.x * 256 + threadIdx.x;
    if (i >= BQ * LQ * N_MFCC) return;
    int m = i % N_MFCC;
    int t = i / N_MFCC;
    g_xc[(size_t)t * DQ + VID_FEAT + m] = a[i];
}

__global__ void k_lastcol() {   // g_xb = g_xc[:, L-1, :]
    int i = blockIdx.x * 256 + threadIdx.x;
    if (i < BQ * DQ) {
        int b = i >> 8, d = i & 255;
        g_xb[i] = g_xc[(size_t)(b * LQ + LQ - 1) * DQ + d];
    }
}

__global__ void k_xlast() {     // concat(xc_fwd[:, -1], xb)
    int i = blockIdx.x * 256 + threadIdx.x;
    if (i < BQ * 2 * DQ) {
        int b = i >> 9, j = i & 511;
        g_xlast[i] = (j < DQ) ? g_xc[(size_t)(b * LQ + LQ - 1) * DQ + j]
                              : g_xb[b * DQ + j - DQ];
    }
}

// ---------------------------------------------------------------------------
// RMSNorm over D=256, one block per token
// ---------------------------------------------------------------------------
__global__ void __launch_bounds__(256) k_rms(const float* __restrict__ x,
                                             const float* __restrict__ w,
                                             float* __restrict__ out) {
    int t = blockIdx.x;
    float v = x[(size_t)t * DQ + threadIdx.x];
    float s = v * v;
#pragma unroll
    for (int off = 16; off > 0; off >>= 1) s += __shfl_xor_sync(~0u, s, off);
    __shared__ float red[8];
    if ((threadIdx.x & 31) == 0) red[threadIdx.x >> 5] = s;
    __syncthreads();
    float tot = red[0] + red[1] + red[2] + red[3] +
                red[4] + red[5] + red[6] + red[7];
    float inv = rsqrtf(tot * (1.0f / DQ) + 1e-5f);
    out[(size_t)t * DQ + threadIdx.x] = v * inv * w[threadIdx.x];
}

// ---------------------------------------------------------------------------
// Generic SGEMM: C[M,N] = A[M,K] @ B[N,K]^T (+bias) (+=C if accum)
// ---------------------------------------------------------------------------
__global__ void __launch_bounds__(256) k_gemm(const float* __restrict__ A, int lda,
                                              const float* __restrict__ Bw, int ldb,
                                              float* __restrict__ C, int ldc,
                                              int M, int N, int K,
                                              const float* __restrict__ bias,
                                              int accum) {
    __shared__ float As[16][68];
    __shared__ float Bs[16][68];
    int m0 = blockIdx.y * 64, n0 = blockIdx.x * 64;
    int ty = threadIdx.x >> 4, tx = threadIdx.x & 15;
    float acc[4][4] = {};
    for (int k0 = 0; k0 < K; k0 += 16) {
        for (int i = threadIdx.x; i < 1024; i += 256) {
            int r = i >> 4, kk = i & 15;
            int gk = k0 + kk;
            As[kk][r] = (m0 + r < M && gk < K) ? A[(size_t)(m0 + r) * lda + gk] : 0.f;
            Bs[kk][r] = (n0 + r < N && gk < K) ? Bw[(size_t)(n0 + r) * ldb + gk] : 0.f;
        }
        __syncthreads();
#pragma unroll
        for (int kk = 0; kk < 16; ++kk) {
            float4 av = *reinterpret_cast<const float4*>(&As[kk][ty * 4]);
            float4 bv = *reinterpret_cast<const float4*>(&Bs[kk][tx * 4]);
            float a[4] = {av.x, av.y, av.z, av.w};
            float b[4] = {bv.x, bv.y, bv.z, bv.w};
#pragma unroll
            for (int i = 0; i < 4; ++i)
#pragma unroll
                for (int j = 0; j < 4; ++j) acc[i][j] += a[i] * b[j];
        }
        __syncthreads();
    }
#pragma unroll
    for (int i = 0; i < 4; ++i) {
        int r = m0 + ty * 4 + i;
        if (r >= M) continue;
#pragma unroll
        for (int j = 0; j < 4; ++j) {
            int c = n0 + tx * 4 + j;
            if (c >= N) continue;
            float v = acc[i][j];
            if (bias) v += bias[c];
            if (accum) v += C[(size_t)r * ldc + c];
            C[(size_t)r * ldc + c] = v;
        }
    }
}

// ---------------------------------------------------------------------------
// causal depthwise conv4 + silu   (reads g_xz x-half, writes g_xcs)
// ---------------------------------------------------------------------------
__global__ void k_convsilu(const float* __restrict__ cw,
                           const float* __restrict__ cb, int T, int Lc) {
    int i = blockIdx.x * 256 + threadIdx.x;
    if (i >= T * EDQ) return;
    int t = i >> 9, e = i & 511;
    int l = t % Lc;
    float acc = cb[e];
#pragma unroll
    for (int k = 0; k < 4; ++k) {
        int li = l + k - 3;
        if (li >= 0) acc += g_xz[(size_t)(t + k - 3) * 1024 + e] * cw[e * 4 + k];
    }
    acc = acc / (1.f + __expf(-acc));
    g_xcs[i] = acc;
}

// ---------------------------------------------------------------------------
// Selective scan (fused softplus + D*x + silu(z) gating)
// thread per (b, e) channel, 16 states in registers
// ---------------------------------------------------------------------------
__global__ void __launch_bounds__(128) k_scan(const float* __restrict__ A_log,
                                              const float* __restrict__ Dp, int Lc) {
    int e = blockIdx.x * 128 + threadIdx.x;
    int b = blockIdx.y;
    float negA[NSTQ];
#pragma unroll
    for (int n = 0; n < NSTQ; ++n) negA[n] = -__expf(A_log[e * NSTQ + n]);
    float Dv = Dp[e];
    float h[NSTQ];
#pragma unroll
    for (int n = 0; n < NSTQ; ++n) h[n] = 0.f;
    for (int t = 0; t < Lc; ++t) {
        size_t idx = (size_t)(b * Lc + t);
        float draw = g_delta[idx * EDQ + e];
        float dlt = (draw > 20.f) ? draw : log1pf(__expf(draw));
        float xv  = g_xcs[idx * EDQ + e];
        float z   = g_xz[idx * 1024 + EDQ + e];
        const float* bc = g_dbc + idx * 48;
        float dx = dlt * xv;
        float y = 0.f;
#pragma unroll
        for (int n = 0; n < NSTQ; ++n) {
            float hn = __expf(dlt * negA[n]) * h[n] + dx * __ldg(bc + 16 + n);
            h[n] = hn;
            y += hn * __ldg(bc + 32 + n);
        }
        float sz = z / (1.f + __expf(-z));
        g_ys[idx * EDQ + e] = (y + Dv * xv) * sz;
    }
}

// ---------------------------------------------------------------------------
// Host-side driver
// ---------------------------------------------------------------------------
static float* symf(const void* s) {
    void* p = nullptr;
    cudaGetSymbolAddress(&p, s);
    return (float*)p;
}

static void mamba_layer(float* x, const float* const* p, int l, int Bsz, int Lc) {
    const float* norm_w = p[0] + (size_t)l * DQ;
    const float* in_w   = p[1] + (size_t)l * 2 * EDQ * DQ;
    const float* conv_w = p[2] + (size_t)l * EDQ * 4;
    const float* conv_b = p[3] + (size_t)l * EDQ;
    const float* xp_w   = p[4] + (size_t)l * (DTRQ + 2 * NSTQ) * EDQ;
    const float* dt_w   = p[5] + (size_t)l * EDQ * DTRQ;
    const float* dt_b   = p[6] + (size_t)l * EDQ;
    const float* A_log  = p[7] + (size_t)l * EDQ * NSTQ;
    const float* Dp     = p[8] + (size_t)l * EDQ;
    const float* out_w  = p[9] + (size_t)l * DQ * EDQ;

    int T = Bsz * Lc;
    float* xn    = symf(g_xn);
    float* xz    = symf(g_xz);
    float* xcs   = symf(g_xcs);
    float* dbc   = symf(g_dbc);
    float* delta = symf(g_delta);
    float* ys    = symf(g_ys);

    int mt = (T + 63) / 64;
    k_rms<<<T, 256>>>(x, norm_w, xn);
    k_gemm<<<dim3(16, mt), 256>>>(xn, DQ, in_w, DQ, xz, 1024, T, 1024, DQ, nullptr, 0);
    k_convsilu<<<(T * EDQ + 255) / 256, 256>>>(conv_w, conv_b, T, Lc);
    k_gemm<<<dim3(1, mt), 256>>>(xcs, EDQ, xp_w, EDQ, dbc, 48, T, 48, EDQ, nullptr, 0);
    k_gemm<<<dim3(8, mt), 256>>>(dbc, 48, dt_w, DTRQ, delta, EDQ, T, EDQ, DTRQ, dt_b, 0);
    k_scan<<<dim3(EDQ / 128, Bsz), 128>>>(A_log, Dp, Lc);
    k_gemm<<<dim3(4, mt), 256>>>(ys, EDQ, out_w, EDQ, x, DQ, T, DQ, EDQ, nullptr, 1);
}

extern "C" void kernel_launch(void* const* d_in, const int* in_sizes, int n_in,
                              void* d_out, int out_size) {
    const float* video = (const float*)d_in[0];
    const float* audio = (const float*)d_in[1];
    const float* c1w = (const float*)d_in[2];
    const float* c1b = (const float*)d_in[3];
    const float* c2w = (const float*)d_in[4];
    const float* c2b = (const float*)d_in[5];
    const float* fcw = (const float*)d_in[6];
    const float* fcb = (const float*)d_in[7];
    const float* fwdp[10];
    const float* bwdp[10];
    for (int i = 0; i < 10; ++i) fwdp[i] = (const float*)d_in[8 + i];
    for (int i = 0; i < 10; ++i) bwdp[i] = (const float*)d_in[18 + i];
    const float* fc_w  = (const float*)d_in[28];
    const float* fc_b  = (const float*)d_in[29];
    const float* fc2_w = (const float*)d_in[30];
    const float* fc2_b = (const float*)d_in[31];
    float* out = (float*)d_out;

    cudaFuncSetAttribute(k_conv1, cudaFuncAttributeMaxDynamicSharedMemorySize, 53248);
    cudaFuncSetAttribute(k_conv2_mma, cudaFuncAttributeMaxDynamicSharedMemorySize,
                         C2_SMEM_BYTES);

    // ---- CNN ----
    k_conv1<<<NIMG, 256, 52736>>>(video, c1w, c1b);
    k_conv2_mma<<<NIMG, 256, C2_SMEM_BYTES>>>(c2w, c2b);
    k_cnnfc<<<NIMG, 256>>>(fcw, fcb);
    k_audio<<<(BQ * LQ * N_MFCC + 255) / 256, 256>>>(audio);

    float* xc    = symf(g_xc);
    float* xb    = symf(g_xb);
    float* xlast = symf(g_xlast);
    float* fc1   = symf(g_fc1);

    // ---- backward input snapshot (causal => only last timestep matters) ----
    k_lastcol<<<(BQ * DQ + 255) / 256, 256>>>();

    // ---- forward Mamba, in-place on g_xc ----
    for (int l = 0; l < NLQ; ++l) mamba_layer(xc, fwdp, l, BQ, LQ);

    // ---- backward Mamba on single timestep ----
    for (int l = 0; l < NLQ; ++l) mamba_layer(xb, bwdp, l, BQ, 1);

    // ---- head ----
    k_xlast<<<(BQ * 2 * DQ + 255) / 256, 256>>>();
    k_gemm<<<dim3(4, 1), 256>>>(xlast, 2 * DQ, fc_w, 2 * DQ, fc1, DQ,
                                BQ, DQ, 2 * DQ, fc_b, 0);
    k_gemm<<<dim3(1, 1), 256>>>(fc1, DQ, fc2_w, DQ, out, 2,
                                BQ, 2, DQ, fc2_b, 0);
}